// round 13
// baseline (speedup 1.0000x reference)
#include <cuda_runtime.h>
#include <cuda_fp16.h>
#include <math.h>
#include <stdint.h>

// Problem constants
#define NTOK 4096
#define DD   512
#define HH   256
#define NE   16
#define FF   2048
#define TOPK 2

// GEMM tiling (mma.sync path)
#define TMr   128         // CTA M tile
#define TNc   128         // CTA N tile
#define CK    32          // K elements per chunk
#define STAGES 5
#define KSPLIT 4          // split-K for k_down
#define NROWTILES 80
#define MAXP (NROWTILES * TMr)

// SMEM layout: bias (512B) then STAGES stage buffers (A_HI, A_LO, B_HI)
#define ROWB   80                       // padded row stride bytes (32 fp16 + 16B pad)
#define TILEB  (128 * ROWB)             // 10240 bytes per tile
#define A_HI   0
#define A_LO   (1 * TILEB)
#define B_HI   (2 * TILEB)
#define STAGE_SZ (3 * TILEB)            // 30720
#define SM_BUF 512
#define SMEM_DYN (SM_BUF + STAGES * STAGE_SZ)   // 154112

// ---------------- device scratch (static, allocation-free) ----------------
__device__ float g_h[NTOK * HH];
__device__ __half g_xh[NTOK * DD];
__device__ __half g_xl[NTOK * DD];
__device__ __half g_upwt[(size_t)NE * FF * DD];   // [e][f][d] fp16
__device__ __half g_dwwt[(size_t)NE * DD * FF];   // [e][d][f] fp16
__device__ __half g_hid_hi[(size_t)MAXP * FF];
__device__ __half g_hid_lo[(size_t)MAXP * FF];
__device__ float g_partial[TOPK * KSPLIT][(size_t)NTOK * DD];
__device__ int   g_top_idx[NTOK * TOPK];
__device__ float g_top_w[NTOK * TOPK];
__device__ int   g_count[NE];
__device__ int   g_fill[NE];
__device__ int   g_off[NE + 1];
__device__ float g_usage[NE];
__device__ int   g_row_token[MAXP];
__device__ float g_row_wt[MAXP];
__device__ int   g_row_expert[MAXP];
__device__ int   g_row_slot[MAXP];

// ---------------- helpers ----------------
__device__ __forceinline__ uint32_t smem_u32(const void* p) {
    uint32_t a;
    asm("{ .reg .u64 t; cvta.to.shared.u64 t, %1; cvt.u32.u64 %0, t; }" : "=r"(a) : "l"(p));
    return a;
}
__device__ __forceinline__ void cpa16(uint32_t dst, const void* src, uint32_t srcsize) {
    asm volatile("cp.async.cg.shared.global [%0], [%1], 16, %2;"
                 :: "r"(dst), "l"(src), "r"(srcsize) : "memory");
}
__device__ __forceinline__ void cpa_commit() {
    asm volatile("cp.async.commit_group;" ::: "memory");
}
__device__ __forceinline__ void cpa_waitS() {
    asm volatile("cp.async.wait_group 3;" ::: "memory");   // STAGES-2
}
__device__ __forceinline__ void ldm4(uint32_t* r, uint32_t addr) {
    asm volatile("ldmatrix.sync.aligned.m8n8.x4.shared.b16 {%0,%1,%2,%3}, [%4];"
                 : "=r"(r[0]), "=r"(r[1]), "=r"(r[2]), "=r"(r[3]) : "r"(addr));
}
__device__ __forceinline__ void mma16816(float* c, const uint32_t* a, uint32_t b0, uint32_t b1) {
    asm volatile(
        "mma.sync.aligned.m16n8k16.row.col.f32.f16.f16.f32 "
        "{%0,%1,%2,%3}, {%4,%5,%6,%7}, {%8,%9}, {%0,%1,%2,%3};"
        : "+f"(c[0]), "+f"(c[1]), "+f"(c[2]), "+f"(c[3])
        : "r"(a[0]), "r"(a[1]), "r"(a[2]), "r"(a[3]), "r"(b0), "r"(b1));
}
__device__ __forceinline__ void splitpack_h(float a, float b, uint32_t& h, uint32_t& l) {
    __half ha = __float2half_rn(a);
    __half hb = __float2half_rn(b);
    __half la = __float2half_rn(a - __half2float(ha));
    __half lb = __float2half_rn(b - __half2float(hb));
    __half2 hp = __halves2half2(ha, hb);
    __half2 lp = __halves2half2(la, lb);
    h = *(uint32_t*)&hp; l = *(uint32_t*)&lp;
}
__device__ __forceinline__ uint32_t packh(float a, float b) {
    __half2 p = __halves2half2(__float2half_rn(a), __float2half_rn(b));
    return *(uint32_t*)&p;
}
__device__ __forceinline__ float gelu_f(float v) {
    return 0.5f * v * (1.f + erff(v * 0.70710678118f));
}

// ---------------- init counters ----------------
__global__ void k_init() {
    if (threadIdx.x < NE) {
        g_count[threadIdx.x] = 0;
        g_fill[threadIdx.x]  = 0;
        g_usage[threadIdx.x] = 0.f;
    }
}

// ---------------- split x into fp16 hi/lo ----------------
__global__ void k_split_x(const float* __restrict__ x) {
    int i = blockIdx.x * blockDim.x + threadIdx.x;  // NTOK*DD/4
    float4 v = ((const float4*)x)[i];
    uint32_t h0, l0, h1, l1;
    splitpack_h(v.x, v.y, h0, l0);
    splitpack_h(v.z, v.w, h1, l1);
    ((uint2*)g_xh)[i] = make_uint2(h0, h1);
    ((uint2*)g_xl)[i] = make_uint2(l0, l1);
}

// ---------------- weight convert+transpose: [E][R][C] f32 -> [E][C][R] fp16 ----------------
__global__ void k_wconv(const float* __restrict__ src,
                        __half* __restrict__ dhi,
                        int R, int C) {
    __shared__ float tile[64][33];
    const int e  = blockIdx.z;
    const int r0 = blockIdx.y * 64;
    const int c0 = blockIdx.x * 32;
    const int tx = threadIdx.x, ty = threadIdx.y;
    const float* s = src + ((size_t)e * R + r0) * C + c0;
#pragma unroll
    for (int i = 0; i < 8; i++)
        tile[ty + 8 * i][tx] = s[(size_t)(ty + 8 * i) * C + tx];
    __syncthreads();
#pragma unroll
    for (int i = 0; i < 4; i++) {
        int cc = ty + 8 * i;
        float va = tile[2 * tx][cc];
        float vb = tile[2 * tx + 1][cc];
        size_t o = ((size_t)e * C + c0 + cc) * R + r0 + 2 * tx;
        *(uint32_t*)(dhi + o) = packh(va, vb);
    }
}

// ---------------- gate GEMM1: g_h = relu(x @ w1 + b1) (fp32 — exact routing) ----------------
__global__ __launch_bounds__(256) void k_gate1(const float* __restrict__ A,
                                               const float* __restrict__ W,
                                               const float* __restrict__ bias) {
    __shared__ float As[16][128];
    __shared__ float Bs[16][64];
    const int tid  = threadIdx.x;
    const int tx   = tid & 15, ty = tid >> 4;
    const int rowb = blockIdx.y * 128;
    const int colb = blockIdx.x * 64;
    const int ar = tid >> 2;
    const int ak = (tid & 3) << 2;
    const int bk = tid >> 4;
    const int bc = (tid & 15) << 2;

    float acc[8][4];
#pragma unroll
    for (int i = 0; i < 8; i++)
#pragma unroll
        for (int j = 0; j < 4; j++) acc[i][j] = 0.f;

    for (int k0 = 0; k0 < DD; k0 += 16) {
        float4 a0 = *(const float4*)(A + (size_t)(rowb + ar) * DD + k0 + ak);
        float4 a1 = *(const float4*)(A + (size_t)(rowb + ar + 64) * DD + k0 + ak);
        As[ak + 0][ar] = a0.x; As[ak + 1][ar] = a0.y; As[ak + 2][ar] = a0.z; As[ak + 3][ar] = a0.w;
        As[ak + 0][ar + 64] = a1.x; As[ak + 1][ar + 64] = a1.y; As[ak + 2][ar + 64] = a1.z; As[ak + 3][ar + 64] = a1.w;
        *(float4*)&Bs[bk][bc] = *(const float4*)(W + (size_t)(k0 + bk) * HH + colb + bc);
        __syncthreads();
#pragma unroll
        for (int kk = 0; kk < 16; kk++) {
            float4 r0 = *(const float4*)&As[kk][ty * 8];
            float4 r1 = *(const float4*)&As[kk][ty * 8 + 4];
            float4 bv = *(const float4*)&Bs[kk][tx * 4];
            float av[8] = {r0.x, r0.y, r0.z, r0.w, r1.x, r1.y, r1.z, r1.w};
            float bb[4] = {bv.x, bv.y, bv.z, bv.w};
#pragma unroll
            for (int i = 0; i < 8; i++)
#pragma unroll
                for (int j = 0; j < 4; j++) acc[i][j] += av[i] * bb[j];
        }
        __syncthreads();
    }
    float b0 = bias[colb + tx * 4 + 0];
    float b1v = bias[colb + tx * 4 + 1];
    float b2v = bias[colb + tx * 4 + 2];
    float b3v = bias[colb + tx * 4 + 3];
#pragma unroll
    for (int i = 0; i < 8; i++) {
        float4 v;
        v.x = fmaxf(acc[i][0] + b0, 0.f);
        v.y = fmaxf(acc[i][1] + b1v, 0.f);
        v.z = fmaxf(acc[i][2] + b2v, 0.f);
        v.w = fmaxf(acc[i][3] + b3v, 0.f);
        *(float4*)&g_h[(size_t)(rowb + ty * 8 + i) * HH + colb + tx * 4] = v;
    }
}

// ---------------- router ----------------
__global__ __launch_bounds__(256) void k_router(const float* __restrict__ w2,
                                                const float* __restrict__ b2,
                                                float* __restrict__ probs_out) {
    __shared__ float hs[16 * HH];
    __shared__ float w2s[HH * NE];
    __shared__ float usage_s[NE];
    const int tid  = threadIdx.x;
    const int tok0 = blockIdx.x * 16;
    for (int i = tid; i < 16 * HH; i += 256) hs[i] = g_h[(size_t)tok0 * HH + i];
    for (int i = tid; i < HH * NE; i += 256) w2s[i] = w2[i];
    if (tid < NE) usage_s[tid] = 0.f;
    __syncthreads();

    const int tl = tid >> 4;
    const int e  = tid & 15;
    float s = b2[e];
    const float* hr = &hs[tl * HH];
#pragma unroll 8
    for (int k = 0; k < HH; k++) s += hr[k] * w2s[k * NE + e];

    float z = s * 2.0f;
    float m = z;
#pragma unroll
    for (int off = 8; off; off >>= 1) m = fmaxf(m, __shfl_xor_sync(0xffffffffu, m, off, 16));
    float p = expf(z - m);
    float sum = p;
#pragma unroll
    for (int off = 8; off; off >>= 1) sum += __shfl_xor_sync(0xffffffffu, sum, off, 16);
    float prob = p / sum;

    const int tok = tok0 + tl;
    probs_out[(size_t)tok * NE + e] = prob;
    atomicAdd(&usage_s[e], prob);

    float v1 = prob; int i1 = e;
#pragma unroll
    for (int off = 8; off; off >>= 1) {
        float ov = __shfl_xor_sync(0xffffffffu, v1, off, 16);
        int   oi = __shfl_xor_sync(0xffffffffu, i1, off, 16);
        if (ov > v1 || (ov == v1 && oi < i1)) { v1 = ov; i1 = oi; }
    }
    float v2 = (e == i1) ? -1e30f : prob; int i2 = e;
#pragma unroll
    for (int off = 8; off; off >>= 1) {
        float ov = __shfl_xor_sync(0xffffffffu, v2, off, 16);
        int   oi = __shfl_xor_sync(0xffffffffu, i2, off, 16);
        if (ov > v2 || (ov == v2 && oi < i2)) { v2 = ov; i2 = oi; }
    }
    if (e == 0) {
        float e2  = expf(v2 - v1);
        float den = 1.f + e2;
        g_top_idx[tok * 2 + 0] = i1;
        g_top_idx[tok * 2 + 1] = i2;
        g_top_w[tok * 2 + 0] = 1.f / den;
        g_top_w[tok * 2 + 1] = e2 / den;
        atomicAdd(&g_count[i1], 1);
        atomicAdd(&g_count[i2], 1);
    }
    __syncthreads();
    if (tid < NE) atomicAdd(&g_usage[tid], usage_s[tid]);
}

// ---------------- offsets + scatter ----------------
__global__ void k_offsets() {
    __shared__ int soff[NE + 1];
    if (threadIdx.x == 0) {
        int acc = 0;
        for (int ee = 0; ee < NE; ee++) {
            soff[ee] = acc;
            acc += ((g_count[ee] + TMr - 1) / TMr) * TMr;
        }
        soff[NE] = acc;
        for (int ee = 0; ee <= NE; ee++) g_off[ee] = soff[ee];
    }
    __syncthreads();
    for (int i = threadIdx.x; i < MAXP; i += blockDim.x) {
        g_row_token[i] = -1;
        int ee = 0;
        while (ee < NE - 1 && i >= soff[ee + 1]) ee++;
        g_row_expert[i] = ee;
    }
}

__global__ void k_scatter() {
    int tok = blockIdx.x * blockDim.x + threadIdx.x;
    if (tok >= NTOK) return;
#pragma unroll
    for (int k = 0; k < TOPK; k++) {
        int   e = g_top_idx[tok * 2 + k];
        float w = g_top_w[tok * 2 + k];
        int pos = g_off[e] + atomicAdd(&g_fill[e], 1);
        g_row_token[pos] = tok;
        g_row_wt[pos]    = w;
        g_row_slot[pos]  = k;
    }
}

// ================= mma.sync GEMM kernels (fp16 2-term) =================
__device__ __forceinline__ void gemm_compute_chunk(uint32_t sb, int s,
                                                   uint32_t aOff, uint32_t bOff,
                                                   float acc[4][4][4]) {
    const uint32_t baseAh = sb + SM_BUF + s * STAGE_SZ + A_HI;
    const uint32_t baseAl = sb + SM_BUF + s * STAGE_SZ + A_LO;
    const uint32_t baseBh = sb + SM_BUF + s * STAGE_SZ + B_HI;
#pragma unroll
    for (int k16 = 0; k16 < 2; k16++) {
        const uint32_t kb = k16 * 32;
        uint32_t bh0[4], bh1[4];
        ldm4(bh0, baseBh + bOff + kb);
        ldm4(bh1, baseBh + bOff + 16 * ROWB + kb);
#pragma unroll
        for (int mf = 0; mf < 4; mf++) {
            uint32_t ah[4], al[4];
            ldm4(ah, baseAh + aOff + mf * (16 * ROWB) + kb);
            ldm4(al, baseAl + aOff + mf * (16 * ROWB) + kb);
            mma16816(acc[mf][0], ah, bh0[0], bh0[2]);
            mma16816(acc[mf][0], al, bh0[0], bh0[2]);
            mma16816(acc[mf][1], ah, bh0[1], bh0[3]);
            mma16816(acc[mf][1], al, bh0[1], bh0[3]);
            mma16816(acc[mf][2], ah, bh1[0], bh1[2]);
            mma16816(acc[mf][2], al, bh1[0], bh1[2]);
            mma16816(acc[mf][3], ah, bh1[1], bh1[3]);
            mma16816(acc[mf][3], al, bh1[1], bh1[3]);
        }
    }
}

// ---------------- up: gathered x @ up_w^T + bias -> gelu -> g_hid hi/lo ----------------
__global__ __launch_bounds__(256, 1) void k_up(const float* __restrict__ upb) {
    extern __shared__ char smem[];
    const int rowb = blockIdx.y * TMr;
    if (rowb >= g_off[NE]) return;
    const int e    = g_row_expert[rowb];
    const int colb = blockIdx.x * TNc;
    const uint32_t sb = smem_u32(smem);
    const int tid = threadIdx.x, lane = tid & 31, wid = tid >> 5;
    const int warpM = wid >> 2, warpN = wid & 3;

    float* sBias = (float*)smem;
    if (tid < TNc) sBias[tid] = upb[(size_t)e * FF + colb + tid];

    const int irow = tid >> 1, ihalf = tid & 1;
    const int tok = g_row_token[rowb + irow];
    const uint32_t okA = (tok >= 0) ? 16u : 0u;
    const __half* sAh = g_xh + (size_t)(tok < 0 ? 0 : tok) * DD;
    const __half* sAl = g_xl + (size_t)(tok < 0 ? 0 : tok) * DD;
    const __half* sBh = g_upwt + ((size_t)e * FF + colb + irow) * DD;
    const uint32_t dRow = sb + SM_BUF + irow * ROWB + ihalf * 32;

    float acc[4][4][4];
#pragma unroll
    for (int a = 0; a < 4; a++)
#pragma unroll
        for (int b = 0; b < 4; b++)
#pragma unroll
            for (int c = 0; c < 4; c++) acc[a][b][c] = 0.f;

    const int NC = DD / CK;  // 16
#pragma unroll 1
    for (int c = 0; c < STAGES - 1; c++) {
        const int k0 = c * CK + ihalf * 16;
        const uint32_t st = dRow + (c % STAGES) * STAGE_SZ;
        cpa16(st + A_HI,      sAh + k0,     okA);
        cpa16(st + A_HI + 16, sAh + k0 + 8, okA);
        cpa16(st + A_LO,      sAl + k0,     okA);
        cpa16(st + A_LO + 16, sAl + k0 + 8, okA);
        cpa16(st + B_HI,      sBh + k0,     16);
        cpa16(st + B_HI + 16, sBh + k0 + 8, 16);
        cpa_commit();
    }

    const uint32_t lrow = lane & 15, lcol = (lane >> 4) * 16;
    const uint32_t aOff = (warpM * 64 + lrow) * ROWB + lcol;
    const uint32_t bOff = (warpN * 32 + lrow) * ROWB + lcol;

#pragma unroll 1
    for (int c = 0; c < NC; c++) {
        cpa_waitS();
        __syncthreads();
        const int nc = c + STAGES - 1;
        if (nc < NC) {
            const int k0 = nc * CK + ihalf * 16;
            const uint32_t st = dRow + (nc % STAGES) * STAGE_SZ;
            cpa16(st + A_HI,      sAh + k0,     okA);
            cpa16(st + A_HI + 16, sAh + k0 + 8, okA);
            cpa16(st + A_LO,      sAl + k0,     okA);
            cpa16(st + A_LO + 16, sAl + k0 + 8, okA);
            cpa16(st + B_HI,      sBh + k0,     16);
            cpa16(st + B_HI + 16, sBh + k0 + 8, 16);
        }
        cpa_commit();
        gemm_compute_chunk(sb, c % STAGES, aOff, bOff, acc);
    }

    // epilogue: bias + GELU -> g_hid hi/lo (fp16)
    const int g = lane >> 2, tq = lane & 3;
#pragma unroll
    for (int mf = 0; mf < 4; mf++) {
        const size_t r0 = (size_t)(rowb + warpM * 64 + mf * 16 + g);
#pragma unroll
        for (int nf = 0; nf < 4; nf++) {
            const int cl = warpN * 32 + nf * 8 + 2 * tq;
            const float b0 = sBias[cl], b1 = sBias[cl + 1];
            float v0 = gelu_f(acc[mf][nf][0] + b0);
            float v1 = gelu_f(acc[mf][nf][1] + b1);
            float v2 = gelu_f(acc[mf][nf][2] + b0);
            float v3 = gelu_f(acc[mf][nf][3] + b1);
            uint32_t h, l;
            splitpack_h(v0, v1, h, l);
            *(uint32_t*)(g_hid_hi + r0 * FF + colb + cl) = h;
            *(uint32_t*)(g_hid_lo + r0 * FF + colb + cl) = l;
            splitpack_h(v2, v3, h, l);
            *(uint32_t*)(g_hid_hi + (r0 + 8) * FF + colb + cl) = h;
            *(uint32_t*)(g_hid_lo + (r0 + 8) * FF + colb + cl) = l;
        }
    }
}

// ---------------- down (split-K): hid @ down_w^T (+ bias at ks==0), weighted partials ----------------
__global__ __launch_bounds__(256, 1) void k_down(const float* __restrict__ dwb) {
    extern __shared__ char smem[];
    const int rowb = blockIdx.y * TMr;
    if (rowb >= g_off[NE]) return;
    const int e    = g_row_expert[rowb];
    const int colb = blockIdx.x * TNc;
    const int ks   = blockIdx.z;
    const int kbase = ks * (FF / KSPLIT);   // 512-wide K slices
    const uint32_t sb = smem_u32(smem);
    const int tid = threadIdx.x, lane = tid & 31, wid = tid >> 5;
    const int warpM = wid >> 2, warpN = wid & 3;

    float* sBias = (float*)smem;
    if (tid < TNc) sBias[tid] = (ks == 0) ? dwb[(size_t)e * DD + colb + tid] : 0.f;

    const int irow = tid >> 1, ihalf = tid & 1;
    const __half* sAh = g_hid_hi + (size_t)(rowb + irow) * FF + kbase;
    const __half* sAl = g_hid_lo + (size_t)(rowb + irow) * FF + kbase;
    const __half* sBh = g_dwwt + ((size_t)e * DD + colb + irow) * FF + kbase;
    const uint32_t dRow = sb + SM_BUF + irow * ROWB + ihalf * 32;

    float acc[4][4][4];
#pragma unroll
    for (int a = 0; a < 4; a++)
#pragma unroll
        for (int b = 0; b < 4; b++)
#pragma unroll
            for (int c = 0; c < 4; c++) acc[a][b][c] = 0.f;

    const int NC = (FF / KSPLIT) / CK;  // 16
#pragma unroll 1
    for (int c = 0; c < STAGES - 1; c++) {
        const int k0 = c * CK + ihalf * 16;
        const uint32_t st = dRow + (c % STAGES) * STAGE_SZ;
        cpa16(st + A_HI,      sAh + k0,     16);
        cpa16(st + A_HI + 16, sAh + k0 + 8, 16);
        cpa16(st + A_LO,      sAl + k0,     16);
        cpa16(st + A_LO + 16, sAl + k0 + 8, 16);
        cpa16(st + B_HI,      sBh + k0,     16);
        cpa16(st + B_HI + 16, sBh + k0 + 8, 16);
        cpa_commit();
    }

    const uint32_t lrow = lane & 15, lcol = (lane >> 4) * 16;
    const uint32_t aOff = (warpM * 64 + lrow) * ROWB + lcol;
    const uint32_t bOff = (warpN * 32 + lrow) * ROWB + lcol;

#pragma unroll 1
    for (int c = 0; c < NC; c++) {
        cpa_waitS();
        __syncthreads();
        const int nc = c + STAGES - 1;
        if (nc < NC) {
            const int k0 = nc * CK + ihalf * 16;
            const uint32_t st = dRow + (nc % STAGES) * STAGE_SZ;
            cpa16(st + A_HI,      sAh + k0,     16);
            cpa16(st + A_HI + 16, sAh + k0 + 8, 16);
            cpa16(st + A_LO,      sAl + k0,     16);
            cpa16(st + A_LO + 16, sAl + k0 + 8, 16);
            cpa16(st + B_HI,      sBh + k0,     16);
            cpa16(st + B_HI + 16, sBh + k0 + 8, 16);
        }
        cpa_commit();
        gemm_compute_chunk(sb, c % STAGES, aOff, bOff, acc);
    }

    // epilogue: (+bias at ks==0) * wt, write per-(slot,ks) partials
    const int g = lane >> 2, tq = lane & 3;
#pragma unroll
    for (int mf = 0; mf < 4; mf++) {
        const int rA = rowb + warpM * 64 + mf * 16 + g;
        const int rB = rA + 8;
        const int tokA = g_row_token[rA];
        const int tokB = g_row_token[rB];
        const float wtA = g_row_wt[rA], wtB = g_row_wt[rB];
        const int bufA = ((tokA >= 0) ? g_row_slot[rA] : 0) * KSPLIT + ks;
        const int bufB = ((tokB >= 0) ? g_row_slot[rB] : 0) * KSPLIT + ks;
#pragma unroll
        for (int nf = 0; nf < 4; nf++) {
            const int cl = warpN * 32 + nf * 8 + 2 * tq;
            const float b0 = sBias[cl], b1 = sBias[cl + 1];
            if (tokA >= 0) {
                float2 v = make_float2((acc[mf][nf][0] + b0) * wtA,
                                       (acc[mf][nf][1] + b1) * wtA);
                *(float2*)(&g_partial[bufA][0] + (size_t)tokA * DD + colb + cl) = v;
            }
            if (tokB >= 0) {
                float2 v = make_float2((acc[mf][nf][2] + b0) * wtB,
                                       (acc[mf][nf][3] + b1) * wtB);
                *(float2*)(&g_partial[bufB][0] + (size_t)tokB * DD + colb + cl) = v;
            }
        }
    }
}

// ---------------- combine all partials ----------------
__global__ void k_combine(float* __restrict__ out) {
    int i = blockIdx.x * blockDim.x + threadIdx.x;
    float4 s = make_float4(0.f, 0.f, 0.f, 0.f);
#pragma unroll
    for (int b = 0; b < TOPK * KSPLIT; b++) {
        float4 v = ((const float4*)&g_partial[b][0])[i];
        s.x += v.x; s.y += v.y; s.z += v.z; s.w += v.w;
    }
    ((float4*)out)[i] = s;
}

// ---------------- load-balance loss ----------------
__global__ void k_fin(float* __restrict__ out) {
    int t = threadIdx.x;
    float v = 0.f;
    if (t < NE) {
        float u = g_usage[t] * (1.0f / NTOK);
        float d = u - (1.0f / NE);
        v = d * d;
    }
#pragma unroll
    for (int off = 16; off; off >>= 1) v += __shfl_down_sync(0xffffffffu, v, off);
    if (t == 0) out[(size_t)NTOK * DD] = v * (1.0f / NE);
}

// ---------------- launch ----------------
extern "C" void kernel_launch(void* const* d_in, const int* in_sizes, int n_in,
                              void* d_out, int out_size) {
    const float* x   = (const float*)d_in[0];
    const float* gw1 = (const float*)d_in[1];
    const float* gb1 = (const float*)d_in[2];
    const float* gw2 = (const float*)d_in[3];
    const float* gb2 = (const float*)d_in[4];
    const float* upw = (const float*)d_in[5];
    const float* upb = (const float*)d_in[6];
    const float* dww = (const float*)d_in[7];
    const float* dwb = (const float*)d_in[8];
    float* out   = (float*)d_out;
    float* probs = out + (size_t)NTOK * DD + 1;

    static int smem_set = 0;
    if (!smem_set) {
        cudaFuncSetAttribute(k_up,   cudaFuncAttributeMaxDynamicSharedMemorySize, SMEM_DYN);
        cudaFuncSetAttribute(k_down, cudaFuncAttributeMaxDynamicSharedMemorySize, SMEM_DYN);
        smem_set = 1;
    }

    __half *upwt, *dwwt;
    cudaGetSymbolAddress((void**)&upwt, g_upwt);
    cudaGetSymbolAddress((void**)&dwwt, g_dwwt);

    k_init<<<1, 32>>>();
    k_split_x<<<(NTOK * DD / 4) / 256, 256>>>(x);
    // up_w [E][DD][FF] -> upwt [E][FF][DD]
    k_wconv<<<dim3(FF / 32, DD / 64, NE), dim3(32, 8)>>>(upw, upwt, DD, FF);
    // down_w [E][FF][DD] -> dwwt [E][DD][FF]
    k_wconv<<<dim3(DD / 32, FF / 64, NE), dim3(32, 8)>>>(dww, dwwt, FF, DD);
    k_gate1<<<dim3(HH / 64, NTOK / 128), 256>>>(x, gw1, gb1);
    k_router<<<NTOK / 16, 256>>>(gw2, gb2, probs);
    k_offsets<<<1, 256>>>();
    k_scatter<<<NTOK / 256, 256>>>();
    k_up<<<dim3(FF / TNc, NROWTILES), 256, SMEM_DYN>>>(upb);
    k_down<<<dim3(DD / TNc, NROWTILES, KSPLIT), 256, SMEM_DYN>>>(dwb);
    k_combine<<<(NTOK * DD / 4) / 256, 256>>>(out);
    k_fin<<<1, 32>>>(out);
}

// round 14
// speedup vs baseline: 1.4849x; 1.4849x over previous
#include <cuda_runtime.h>
#include <cuda_fp16.h>
#include <math.h>
#include <stdint.h>

// Problem constants
#define NTOK 4096
#define DD   512
#define HH   256
#define NE   16
#define FF   2048
#define TOPK 2

// GEMM tiling (mma.sync path, single-fp16 A and B)
#define TMr   128         // CTA M tile
#define TNc   128         // CTA N tile
#define CK    32          // K elements per chunk
#define STAGES 6
#define NROWTILES 80
#define MAXP (NROWTILES * TMr)

// SMEM layout: bias (512B) then STAGES stage buffers (A_HI, B_HI)
#define ROWB   80                       // padded row stride bytes (32 fp16 + 16B pad)
#define TILEB  (128 * ROWB)             // 10240 bytes per tile
#define A_HI   0
#define B_HI   (1 * TILEB)
#define STAGE_SZ (2 * TILEB)            // 20480
#define SM_BUF 512
#define SMEM_DYN (SM_BUF + STAGES * STAGE_SZ)   // 123392

// ---------------- device scratch (static, allocation-free) ----------------
__device__ float g_h[NTOK * HH];
__device__ __half g_xh[NTOK * DD];
__device__ __half g_upwt[(size_t)NE * FF * DD];   // [e][f][d] fp16
__device__ __half g_dwwt[(size_t)NE * DD * FF];   // [e][d][f] fp16
__device__ __half g_hid[(size_t)MAXP * FF];
__device__ float g_partial[TOPK][(size_t)NTOK * DD];
__device__ int   g_top_idx[NTOK * TOPK];
__device__ float g_top_w[NTOK * TOPK];
__device__ int   g_count[NE];
__device__ int   g_fill[NE];
__device__ int   g_off[NE + 1];
__device__ float g_usage[NE];
__device__ int   g_row_token[MAXP];
__device__ float g_row_wt[MAXP];
__device__ int   g_row_expert[MAXP];
__device__ int   g_row_slot[MAXP];

// ---------------- helpers ----------------
__device__ __forceinline__ uint32_t smem_u32(const void* p) {
    uint32_t a;
    asm("{ .reg .u64 t; cvta.to.shared.u64 t, %1; cvt.u32.u64 %0, t; }" : "=r"(a) : "l"(p));
    return a;
}
__device__ __forceinline__ void cpa16(uint32_t dst, const void* src, uint32_t srcsize) {
    asm volatile("cp.async.cg.shared.global [%0], [%1], 16, %2;"
                 :: "r"(dst), "l"(src), "r"(srcsize) : "memory");
}
__device__ __forceinline__ void cpa_commit() {
    asm volatile("cp.async.commit_group;" ::: "memory");
}
__device__ __forceinline__ void cpa_waitS() {
    asm volatile("cp.async.wait_group 4;" ::: "memory");   // STAGES-2
}
__device__ __forceinline__ void ldm4(uint32_t* r, uint32_t addr) {
    asm volatile("ldmatrix.sync.aligned.m8n8.x4.shared.b16 {%0,%1,%2,%3}, [%4];"
                 : "=r"(r[0]), "=r"(r[1]), "=r"(r[2]), "=r"(r[3]) : "r"(addr));
}
__device__ __forceinline__ void mma16816(float* c, const uint32_t* a, uint32_t b0, uint32_t b1) {
    asm volatile(
        "mma.sync.aligned.m16n8k16.row.col.f32.f16.f16.f32 "
        "{%0,%1,%2,%3}, {%4,%5,%6,%7}, {%8,%9}, {%0,%1,%2,%3};"
        : "+f"(c[0]), "+f"(c[1]), "+f"(c[2]), "+f"(c[3])
        : "r"(a[0]), "r"(a[1]), "r"(a[2]), "r"(a[3]), "r"(b0), "r"(b1));
}
__device__ __forceinline__ uint32_t packh(float a, float b) {
    __half2 p = __halves2half2(__float2half_rn(a), __float2half_rn(b));
    return *(uint32_t*)&p;
}
__device__ __forceinline__ float gelu_f(float v) {
    return 0.5f * v * (1.f + erff(v * 0.70710678118f));
}

// ---------------- init counters ----------------
__global__ void k_init() {
    if (threadIdx.x < NE) {
        g_count[threadIdx.x] = 0;
        g_fill[threadIdx.x]  = 0;
        g_usage[threadIdx.x] = 0.f;
    }
}

// ---------------- convert x to fp16 ----------------
__global__ void k_cvt_x(const float* __restrict__ x) {
    int i = blockIdx.x * blockDim.x + threadIdx.x;  // NTOK*DD/4
    float4 v = ((const float4*)x)[i];
    ((uint2*)g_xh)[i] = make_uint2(packh(v.x, v.y), packh(v.z, v.w));
}

// ---------------- weight convert+transpose: [E][R][C] f32 -> [E][C][R] fp16 ----------------
__global__ void k_wconv(const float* __restrict__ src,
                        __half* __restrict__ dhi,
                        int R, int C) {
    __shared__ float tile[64][33];
    const int e  = blockIdx.z;
    const int r0 = blockIdx.y * 64;
    const int c0 = blockIdx.x * 32;
    const int tx = threadIdx.x, ty = threadIdx.y;
    const float* s = src + ((size_t)e * R + r0) * C + c0;
#pragma unroll
    for (int i = 0; i < 8; i++)
        tile[ty + 8 * i][tx] = s[(size_t)(ty + 8 * i) * C + tx];
    __syncthreads();
#pragma unroll
    for (int i = 0; i < 4; i++) {
        int cc = ty + 8 * i;
        float va = tile[2 * tx][cc];
        float vb = tile[2 * tx + 1][cc];
        size_t o = ((size_t)e * C + c0 + cc) * R + r0 + 2 * tx;
        *(uint32_t*)(dhi + o) = packh(va, vb);
    }
}

// ---------------- gate GEMM1: g_h = relu(x @ w1 + b1) (fp32 — exact routing) ----------------
__global__ __launch_bounds__(256) void k_gate1(const float* __restrict__ A,
                                               const float* __restrict__ W,
                                               const float* __restrict__ bias) {
    __shared__ float As[16][128];
    __shared__ float Bs[16][64];
    const int tid  = threadIdx.x;
    const int tx   = tid & 15, ty = tid >> 4;
    const int rowb = blockIdx.y * 128;
    const int colb = blockIdx.x * 64;
    const int ar = tid >> 2;
    const int ak = (tid & 3) << 2;
    const int bk = tid >> 4;
    const int bc = (tid & 15) << 2;

    float acc[8][4];
#pragma unroll
    for (int i = 0; i < 8; i++)
#pragma unroll
        for (int j = 0; j < 4; j++) acc[i][j] = 0.f;

    for (int k0 = 0; k0 < DD; k0 += 16) {
        float4 a0 = *(const float4*)(A + (size_t)(rowb + ar) * DD + k0 + ak);
        float4 a1 = *(const float4*)(A + (size_t)(rowb + ar + 64) * DD + k0 + ak);
        As[ak + 0][ar] = a0.x; As[ak + 1][ar] = a0.y; As[ak + 2][ar] = a0.z; As[ak + 3][ar] = a0.w;
        As[ak + 0][ar + 64] = a1.x; As[ak + 1][ar + 64] = a1.y; As[ak + 2][ar + 64] = a1.z; As[ak + 3][ar + 64] = a1.w;
        *(float4*)&Bs[bk][bc] = *(const float4*)(W + (size_t)(k0 + bk) * HH + colb + bc);
        __syncthreads();
#pragma unroll
        for (int kk = 0; kk < 16; kk++) {
            float4 r0 = *(const float4*)&As[kk][ty * 8];
            float4 r1 = *(const float4*)&As[kk][ty * 8 + 4];
            float4 bv = *(const float4*)&Bs[kk][tx * 4];
            float av[8] = {r0.x, r0.y, r0.z, r0.w, r1.x, r1.y, r1.z, r1.w};
            float bb[4] = {bv.x, bv.y, bv.z, bv.w};
#pragma unroll
            for (int i = 0; i < 8; i++)
#pragma unroll
                for (int j = 0; j < 4; j++) acc[i][j] += av[i] * bb[j];
        }
        __syncthreads();
    }
    float b0 = bias[colb + tx * 4 + 0];
    float b1v = bias[colb + tx * 4 + 1];
    float b2v = bias[colb + tx * 4 + 2];
    float b3v = bias[colb + tx * 4 + 3];
#pragma unroll
    for (int i = 0; i < 8; i++) {
        float4 v;
        v.x = fmaxf(acc[i][0] + b0, 0.f);
        v.y = fmaxf(acc[i][1] + b1v, 0.f);
        v.z = fmaxf(acc[i][2] + b2v, 0.f);
        v.w = fmaxf(acc[i][3] + b3v, 0.f);
        *(float4*)&g_h[(size_t)(rowb + ty * 8 + i) * HH + colb + tx * 4] = v;
    }
}

// ---------------- router ----------------
__global__ __launch_bounds__(256) void k_router(const float* __restrict__ w2,
                                                const float* __restrict__ b2,
                                                float* __restrict__ probs_out) {
    __shared__ float hs[16 * HH];
    __shared__ float w2s[HH * NE];
    __shared__ float usage_s[NE];
    const int tid  = threadIdx.x;
    const int tok0 = blockIdx.x * 16;
    for (int i = tid; i < 16 * HH; i += 256) hs[i] = g_h[(size_t)tok0 * HH + i];
    for (int i = tid; i < HH * NE; i += 256) w2s[i] = w2[i];
    if (tid < NE) usage_s[tid] = 0.f;
    __syncthreads();

    const int tl = tid >> 4;
    const int e  = tid & 15;
    float s = b2[e];
    const float* hr = &hs[tl * HH];
#pragma unroll 8
    for (int k = 0; k < HH; k++) s += hr[k] * w2s[k * NE + e];

    float z = s * 2.0f;
    float m = z;
#pragma unroll
    for (int off = 8; off; off >>= 1) m = fmaxf(m, __shfl_xor_sync(0xffffffffu, m, off, 16));
    float p = expf(z - m);
    float sum = p;
#pragma unroll
    for (int off = 8; off; off >>= 1) sum += __shfl_xor_sync(0xffffffffu, sum, off, 16);
    float prob = p / sum;

    const int tok = tok0 + tl;
    probs_out[(size_t)tok * NE + e] = prob;
    atomicAdd(&usage_s[e], prob);

    float v1 = prob; int i1 = e;
#pragma unroll
    for (int off = 8; off; off >>= 1) {
        float ov = __shfl_xor_sync(0xffffffffu, v1, off, 16);
        int   oi = __shfl_xor_sync(0xffffffffu, i1, off, 16);
        if (ov > v1 || (ov == v1 && oi < i1)) { v1 = ov; i1 = oi; }
    }
    float v2 = (e == i1) ? -1e30f : prob; int i2 = e;
#pragma unroll
    for (int off = 8; off; off >>= 1) {
        float ov = __shfl_xor_sync(0xffffffffu, v2, off, 16);
        int   oi = __shfl_xor_sync(0xffffffffu, i2, off, 16);
        if (ov > v2 || (ov == v2 && oi < i2)) { v2 = ov; i2 = oi; }
    }
    if (e == 0) {
        float e2  = expf(v2 - v1);
        float den = 1.f + e2;
        g_top_idx[tok * 2 + 0] = i1;
        g_top_idx[tok * 2 + 1] = i2;
        g_top_w[tok * 2 + 0] = 1.f / den;
        g_top_w[tok * 2 + 1] = e2 / den;
        atomicAdd(&g_count[i1], 1);
        atomicAdd(&g_count[i2], 1);
    }
    __syncthreads();
    if (tid < NE) atomicAdd(&g_usage[tid], usage_s[tid]);
}

// ---------------- offsets + scatter ----------------
__global__ void k_offsets() {
    __shared__ int soff[NE + 1];
    if (threadIdx.x == 0) {
        int acc = 0;
        for (int ee = 0; ee < NE; ee++) {
            soff[ee] = acc;
            acc += ((g_count[ee] + TMr - 1) / TMr) * TMr;
        }
        soff[NE] = acc;
        for (int ee = 0; ee <= NE; ee++) g_off[ee] = soff[ee];
    }
    __syncthreads();
    for (int i = threadIdx.x; i < MAXP; i += blockDim.x) {
        g_row_token[i] = -1;
        int ee = 0;
        while (ee < NE - 1 && i >= soff[ee + 1]) ee++;
        g_row_expert[i] = ee;
    }
}

__global__ void k_scatter() {
    int tok = blockIdx.x * blockDim.x + threadIdx.x;
    if (tok >= NTOK) return;
#pragma unroll
    for (int k = 0; k < TOPK; k++) {
        int   e = g_top_idx[tok * 2 + k];
        float w = g_top_w[tok * 2 + k];
        int pos = g_off[e] + atomicAdd(&g_fill[e], 1);
        g_row_token[pos] = tok;
        g_row_wt[pos]    = w;
        g_row_slot[pos]  = k;
    }
}

// ================= mma.sync GEMM kernels (single fp16 A x B) =================
__device__ __forceinline__ void gemm_compute_chunk(uint32_t sb, int s,
                                                   uint32_t aOff, uint32_t bOff,
                                                   float acc[4][4][4]) {
    const uint32_t baseA = sb + SM_BUF + s * STAGE_SZ + A_HI;
    const uint32_t baseB = sb + SM_BUF + s * STAGE_SZ + B_HI;
#pragma unroll
    for (int k16 = 0; k16 < 2; k16++) {
        const uint32_t kb = k16 * 32;
        uint32_t bh0[4], bh1[4];
        ldm4(bh0, baseB + bOff + kb);
        ldm4(bh1, baseB + bOff + 16 * ROWB + kb);
#pragma unroll
        for (int mf = 0; mf < 4; mf++) {
            uint32_t ah[4];
            ldm4(ah, baseA + aOff + mf * (16 * ROWB) + kb);
            mma16816(acc[mf][0], ah, bh0[0], bh0[2]);
            mma16816(acc[mf][1], ah, bh0[1], bh0[3]);
            mma16816(acc[mf][2], ah, bh1[0], bh1[2]);
            mma16816(acc[mf][3], ah, bh1[1], bh1[3]);
        }
    }
}

// ---------------- up: gathered x @ up_w^T + bias -> gelu -> g_hid fp16 ----------------
__global__ __launch_bounds__(256, 1) void k_up(const float* __restrict__ upb) {
    extern __shared__ char smem[];
    const int rowb = blockIdx.y * TMr;
    if (rowb >= g_off[NE]) return;
    const int e    = g_row_expert[rowb];
    const int colb = blockIdx.x * TNc;
    const uint32_t sb = smem_u32(smem);
    const int tid = threadIdx.x, lane = tid & 31, wid = tid >> 5;
    const int warpM = wid >> 2, warpN = wid & 3;

    float* sBias = (float*)smem;
    if (tid < TNc) sBias[tid] = upb[(size_t)e * FF + colb + tid];

    const int irow = tid >> 1, ihalf = tid & 1;
    const int tok = g_row_token[rowb + irow];
    const uint32_t okA = (tok >= 0) ? 16u : 0u;
    const __half* sA = g_xh + (size_t)(tok < 0 ? 0 : tok) * DD;
    const __half* sB = g_upwt + ((size_t)e * FF + colb + irow) * DD;
    const uint32_t dRow = sb + SM_BUF + irow * ROWB + ihalf * 32;

    float acc[4][4][4];
#pragma unroll
    for (int a = 0; a < 4; a++)
#pragma unroll
        for (int b = 0; b < 4; b++)
#pragma unroll
            for (int c = 0; c < 4; c++) acc[a][b][c] = 0.f;

    const int NC = DD / CK;  // 16
#pragma unroll 1
    for (int c = 0; c < STAGES - 1; c++) {
        const int k0 = c * CK + ihalf * 16;
        const uint32_t st = dRow + (c % STAGES) * STAGE_SZ;
        cpa16(st + A_HI,      sA + k0,     okA);
        cpa16(st + A_HI + 16, sA + k0 + 8, okA);
        cpa16(st + B_HI,      sB + k0,     16);
        cpa16(st + B_HI + 16, sB + k0 + 8, 16);
        cpa_commit();
    }

    const uint32_t lrow = lane & 15, lcol = (lane >> 4) * 16;
    const uint32_t aOff = (warpM * 64 + lrow) * ROWB + lcol;
    const uint32_t bOff = (warpN * 32 + lrow) * ROWB + lcol;

#pragma unroll 1
    for (int c = 0; c < NC; c++) {
        cpa_waitS();
        __syncthreads();
        const int nc = c + STAGES - 1;
        if (nc < NC) {
            const int k0 = nc * CK + ihalf * 16;
            const uint32_t st = dRow + (nc % STAGES) * STAGE_SZ;
            cpa16(st + A_HI,      sA + k0,     okA);
            cpa16(st + A_HI + 16, sA + k0 + 8, okA);
            cpa16(st + B_HI,      sB + k0,     16);
            cpa16(st + B_HI + 16, sB + k0 + 8, 16);
        }
        cpa_commit();
        gemm_compute_chunk(sb, c % STAGES, aOff, bOff, acc);
    }

    // epilogue: bias + GELU -> g_hid fp16
    const int g = lane >> 2, tq = lane & 3;
#pragma unroll
    for (int mf = 0; mf < 4; mf++) {
        const size_t r0 = (size_t)(rowb + warpM * 64 + mf * 16 + g);
#pragma unroll
        for (int nf = 0; nf < 4; nf++) {
            const int cl = warpN * 32 + nf * 8 + 2 * tq;
            const float b0 = sBias[cl], b1 = sBias[cl + 1];
            float v0 = gelu_f(acc[mf][nf][0] + b0);
            float v1 = gelu_f(acc[mf][nf][1] + b1);
            float v2 = gelu_f(acc[mf][nf][2] + b0);
            float v3 = gelu_f(acc[mf][nf][3] + b1);
            *(uint32_t*)(g_hid + r0 * FF + colb + cl) = packh(v0, v1);
            *(uint32_t*)(g_hid + (r0 + 8) * FF + colb + cl) = packh(v2, v3);
        }
    }
}

// ---------------- down: hid @ down_w^T + bias, weighted write to per-slot partials ----------------
__global__ __launch_bounds__(256, 1) void k_down(const float* __restrict__ dwb) {
    extern __shared__ char smem[];
    const int rowb = blockIdx.y * TMr;
    if (rowb >= g_off[NE]) return;
    const int e    = g_row_expert[rowb];
    const int colb = blockIdx.x * TNc;
    const uint32_t sb = smem_u32(smem);
    const int tid = threadIdx.x, lane = tid & 31, wid = tid >> 5;
    const int warpM = wid >> 2, warpN = wid & 3;

    float* sBias = (float*)smem;
    if (tid < TNc) sBias[tid] = dwb[(size_t)e * DD + colb + tid];

    const int irow = tid >> 1, ihalf = tid & 1;
    const __half* sA = g_hid + (size_t)(rowb + irow) * FF;
    const __half* sB = g_dwwt + ((size_t)e * DD + colb + irow) * FF;
    const uint32_t dRow = sb + SM_BUF + irow * ROWB + ihalf * 32;

    float acc[4][4][4];
#pragma unroll
    for (int a = 0; a < 4; a++)
#pragma unroll
        for (int b = 0; b < 4; b++)
#pragma unroll
            for (int c = 0; c < 4; c++) acc[a][b][c] = 0.f;

    const int NC = FF / CK;  // 64
#pragma unroll 1
    for (int c = 0; c < STAGES - 1; c++) {
        const int k0 = c * CK + ihalf * 16;
        const uint32_t st = dRow + (c % STAGES) * STAGE_SZ;
        cpa16(st + A_HI,      sA + k0,     16);
        cpa16(st + A_HI + 16, sA + k0 + 8, 16);
        cpa16(st + B_HI,      sB + k0,     16);
        cpa16(st + B_HI + 16, sB + k0 + 8, 16);
        cpa_commit();
    }

    const uint32_t lrow = lane & 15, lcol = (lane >> 4) * 16;
    const uint32_t aOff = (warpM * 64 + lrow) * ROWB + lcol;
    const uint32_t bOff = (warpN * 32 + lrow) * ROWB + lcol;

#pragma unroll 1
    for (int c = 0; c < NC; c++) {
        cpa_waitS();
        __syncthreads();
        const int nc = c + STAGES - 1;
        if (nc < NC) {
            const int k0 = nc * CK + ihalf * 16;
            const uint32_t st = dRow + (nc % STAGES) * STAGE_SZ;
            cpa16(st + A_HI,      sA + k0,     16);
            cpa16(st + A_HI + 16, sA + k0 + 8, 16);
            cpa16(st + B_HI,      sB + k0,     16);
            cpa16(st + B_HI + 16, sB + k0 + 8, 16);
        }
        cpa_commit();
        gemm_compute_chunk(sb, c % STAGES, aOff, bOff, acc);
    }

    // epilogue: bias + weight, write per-slot partials
    const int g = lane >> 2, tq = lane & 3;
#pragma unroll
    for (int mf = 0; mf < 4; mf++) {
        const int rA = rowb + warpM * 64 + mf * 16 + g;
        const int rB = rA + 8;
        const int tokA = g_row_token[rA];
        const int tokB = g_row_token[rB];
        const float wtA = g_row_wt[rA], wtB = g_row_wt[rB];
        const int slA = (tokA >= 0) ? g_row_slot[rA] : 0;
        const int slB = (tokB >= 0) ? g_row_slot[rB] : 0;
#pragma unroll
        for (int nf = 0; nf < 4; nf++) {
            const int cl = warpN * 32 + nf * 8 + 2 * tq;
            const float b0 = sBias[cl], b1 = sBias[cl + 1];
            if (tokA >= 0) {
                float2 v = make_float2((acc[mf][nf][0] + b0) * wtA,
                                       (acc[mf][nf][1] + b1) * wtA);
                *(float2*)(&g_partial[slA][0] + (size_t)tokA * DD + colb + cl) = v;
            }
            if (tokB >= 0) {
                float2 v = make_float2((acc[mf][nf][2] + b0) * wtB,
                                       (acc[mf][nf][3] + b1) * wtB);
                *(float2*)(&g_partial[slB][0] + (size_t)tokB * DD + colb + cl) = v;
            }
        }
    }
}

// ---------------- combine two slots ----------------
__global__ void k_combine(float* __restrict__ out) {
    int i = blockIdx.x * blockDim.x + threadIdx.x;
    float4 a = ((const float4*)&g_partial[0][0])[i];
    float4 b = ((const float4*)&g_partial[1][0])[i];
    ((float4*)out)[i] = make_float4(a.x + b.x, a.y + b.y, a.z + b.z, a.w + b.w);
}

// ---------------- load-balance loss ----------------
__global__ void k_fin(float* __restrict__ out) {
    int t = threadIdx.x;
    float v = 0.f;
    if (t < NE) {
        float u = g_usage[t] * (1.0f / NTOK);
        float d = u - (1.0f / NE);
        v = d * d;
    }
#pragma unroll
    for (int off = 16; off; off >>= 1) v += __shfl_down_sync(0xffffffffu, v, off);
    if (t == 0) out[(size_t)NTOK * DD] = v * (1.0f / NE);
}

// ---------------- launch ----------------
extern "C" void kernel_launch(void* const* d_in, const int* in_sizes, int n_in,
                              void* d_out, int out_size) {
    const float* x   = (const float*)d_in[0];
    const float* gw1 = (const float*)d_in[1];
    const float* gb1 = (const float*)d_in[2];
    const float* gw2 = (const float*)d_in[3];
    const float* gb2 = (const float*)d_in[4];
    const float* upw = (const float*)d_in[5];
    const float* upb = (const float*)d_in[6];
    const float* dww = (const float*)d_in[7];
    const float* dwb = (const float*)d_in[8];
    float* out   = (float*)d_out;
    float* probs = out + (size_t)NTOK * DD + 1;

    static int smem_set = 0;
    if (!smem_set) {
        cudaFuncSetAttribute(k_up,   cudaFuncAttributeMaxDynamicSharedMemorySize, SMEM_DYN);
        cudaFuncSetAttribute(k_down, cudaFuncAttributeMaxDynamicSharedMemorySize, SMEM_DYN);
        smem_set = 1;
    }

    __half *upwt, *dwwt;
    cudaGetSymbolAddress((void**)&upwt, g_upwt);
    cudaGetSymbolAddress((void**)&dwwt, g_dwwt);

    k_init<<<1, 32>>>();
    k_cvt_x<<<(NTOK * DD / 4) / 256, 256>>>(x);
    // up_w [E][DD][FF] -> upwt [E][FF][DD]
    k_wconv<<<dim3(FF / 32, DD / 64, NE), dim3(32, 8)>>>(upw, upwt, DD, FF);
    // down_w [E][FF][DD] -> dwwt [E][DD][FF]
    k_wconv<<<dim3(DD / 32, FF / 64, NE), dim3(32, 8)>>>(dww, dwwt, FF, DD);
    k_gate1<<<dim3(HH / 64, NTOK / 128), 256>>>(x, gw1, gb1);
    k_router<<<NTOK / 16, 256>>>(gw2, gb2, probs);
    k_offsets<<<1, 256>>>();
    k_scatter<<<NTOK / 256, 256>>>();
    k_up<<<dim3(FF / TNc, NROWTILES), 256, SMEM_DYN>>>(upb);
    k_down<<<dim3(DD / TNc, NROWTILES), 256, SMEM_DYN>>>(dwb);
    k_combine<<<(NTOK * DD / 4) / 256, 256>>>(out);
    k_fin<<<1, 32>>>(out);
}

// round 17
// speedup vs baseline: 1.5557x; 1.0476x over previous
#include <cuda_runtime.h>
#include <cuda_fp16.h>
#include <math.h>
#include <stdint.h>

// Problem constants
#define NTOK 4096
#define DD   512
#define HH   256
#define NE   16
#define FF   2048
#define TOPK 2

// GEMM tiling (mma.sync path, single-fp16 A and B)
#define TMr   128         // CTA M tile
#define TNc   128         // CTA N tile
#define CK    32          // K elements per chunk
#define STAGES 6
#define NROWTILES 80
#define MAXP (NROWTILES * TMr)

// SMEM layout: bias (512B) then STAGES stage buffers (A_HI, B_HI)
#define ROWB   80                       // padded row stride bytes (32 fp16 + 16B pad)
#define TILEB  (128 * ROWB)             // 10240 bytes per tile
#define A_HI   0
#define B_HI   (1 * TILEB)
#define STAGE_SZ (2 * TILEB)            // 20480
#define SM_BUF 512
#define SMEM_DYN (SM_BUF + STAGES * STAGE_SZ)   // 123392

// k_prep block ranges (gate first = long pole)
#define NB_GATE 128                      // (HH/64) x (NTOK/128)
#define NB_WUP  8192                     // (FF/32) x (DD/64) x NE
#define NB_WDN  8192                     // (DD/32) x (FF/64) x NE
#define NB_CVT  2048                     // NTOK*DD/4/256
#define NB_PREP (NB_GATE + NB_WUP + NB_WDN + NB_CVT + 1)

// ---------------- device scratch (static, allocation-free) ----------------
__device__ float g_h[NTOK * HH];
__device__ __half g_xh[NTOK * DD];
__device__ __half g_upwt[(size_t)NE * FF * DD];   // [e][f][d] fp16
__device__ __half g_dwwt[(size_t)NE * DD * FF];   // [e][d][f] fp16
__device__ __half g_hid[(size_t)MAXP * FF];
__device__ float g_partial[TOPK][(size_t)NTOK * DD];
__device__ int   g_top_idx[NTOK * TOPK];
__device__ float g_top_w[NTOK * TOPK];
__device__ int   g_count[NE];
__device__ float g_usage[NE];
__device__ int   g_off[NE + 1];
__device__ int   g_row_token[MAXP];
__device__ float g_row_wt[MAXP];
__device__ int   g_row_expert[MAXP];
__device__ int   g_row_slot[MAXP];

// ---------------- helpers ----------------
__device__ __forceinline__ uint32_t smem_u32(const void* p) {
    uint32_t a;
    asm("{ .reg .u64 t; cvta.to.shared.u64 t, %1; cvt.u32.u64 %0, t; }" : "=r"(a) : "l"(p));
    return a;
}
__device__ __forceinline__ void cpa16(uint32_t dst, const void* src, uint32_t srcsize) {
    asm volatile("cp.async.cg.shared.global [%0], [%1], 16, %2;"
                 :: "r"(dst), "l"(src), "r"(srcsize) : "memory");
}
__device__ __forceinline__ void cpa_commit() {
    asm volatile("cp.async.commit_group;" ::: "memory");
}
__device__ __forceinline__ void cpa_waitS() {
    asm volatile("cp.async.wait_group 4;" ::: "memory");   // STAGES-2
}
__device__ __forceinline__ void ldm4(uint32_t* r, uint32_t addr) {
    asm volatile("ldmatrix.sync.aligned.m8n8.x4.shared.b16 {%0,%1,%2,%3}, [%4];"
                 : "=r"(r[0]), "=r"(r[1]), "=r"(r[2]), "=r"(r[3]) : "r"(addr));
}
__device__ __forceinline__ void mma16816(float* c, const uint32_t* a, uint32_t b0, uint32_t b1) {
    asm volatile(
        "mma.sync.aligned.m16n8k16.row.col.f32.f16.f16.f32 "
        "{%0,%1,%2,%3}, {%4,%5,%6,%7}, {%8,%9}, {%0,%1,%2,%3};"
        : "+f"(c[0]), "+f"(c[1]), "+f"(c[2]), "+f"(c[3])
        : "r"(a[0]), "r"(a[1]), "r"(a[2]), "r"(a[3]), "r"(b0), "r"(b1));
}
__device__ __forceinline__ uint32_t packh(float a, float b) {
    __half2 p = __halves2half2(__float2half_rn(a), __float2half_rn(b));
    return *(uint32_t*)&p;
}
__device__ __forceinline__ float gelu_f(float v) {
    return 0.5f * v * (1.f + erff(v * 0.70710678118f));
}

// ================= merged prelude kernel =================
// blocks [0,128): gate1 | [128, 8320): wconv up | [8320, 16512): wconv down
// [16512, 18560): cvt_x | 18560: init counters

__device__ void wconv_body(const float* __restrict__ src, __half* __restrict__ dst,
                           int R, int C, int bx, int by, int bz, int tid, char* sm) {
    float (*tile)[33] = (float(*)[33])sm;
    const int r0 = by * 64;
    const int c0 = bx * 32;
    const int tx = tid & 31, ty = tid >> 5;
    const float* s = src + ((size_t)bz * R + r0) * C + c0;
#pragma unroll
    for (int i = 0; i < 8; i++)
        tile[ty + 8 * i][tx] = s[(size_t)(ty + 8 * i) * C + tx];
    __syncthreads();
#pragma unroll
    for (int i = 0; i < 4; i++) {
        int cc = ty + 8 * i;
        float va = tile[2 * tx][cc];
        float vb = tile[2 * tx + 1][cc];
        size_t o = ((size_t)bz * C + c0 + cc) * R + r0 + 2 * tx;
        *(uint32_t*)(dst + o) = packh(va, vb);
    }
}

__device__ void gate_body(const float* __restrict__ A, const float* __restrict__ W,
                          const float* __restrict__ bias, int bx, int by, int tid, char* sm) {
    float (*As)[128] = (float(*)[128])sm;
    float (*Bs)[64]  = (float(*)[64])(sm + 16 * 128 * 4);
    const int tx   = tid & 15, ty = tid >> 4;
    const int rowb = by * 128;
    const int colb = bx * 64;
    const int ar = tid >> 2;
    const int ak = (tid & 3) << 2;
    const int bk = tid >> 4;
    const int bc = (tid & 15) << 2;

    float acc[8][4];
#pragma unroll
    for (int i = 0; i < 8; i++)
#pragma unroll
        for (int j = 0; j < 4; j++) acc[i][j] = 0.f;

    for (int k0 = 0; k0 < DD; k0 += 16) {
        float4 a0 = *(const float4*)(A + (size_t)(rowb + ar) * DD + k0 + ak);
        float4 a1 = *(const float4*)(A + (size_t)(rowb + ar + 64) * DD + k0 + ak);
        As[ak + 0][ar] = a0.x; As[ak + 1][ar] = a0.y; As[ak + 2][ar] = a0.z; As[ak + 3][ar] = a0.w;
        As[ak + 0][ar + 64] = a1.x; As[ak + 1][ar + 64] = a1.y; As[ak + 2][ar + 64] = a1.z; As[ak + 3][ar + 64] = a1.w;
        *(float4*)&Bs[bk][bc] = *(const float4*)(W + (size_t)(k0 + bk) * HH + colb + bc);
        __syncthreads();
#pragma unroll
        for (int kk = 0; kk < 16; kk++) {
            float4 r0 = *(const float4*)&As[kk][ty * 8];
            float4 r1 = *(const float4*)&As[kk][ty * 8 + 4];
            float4 bv = *(const float4*)&Bs[kk][tx * 4];
            float av[8] = {r0.x, r0.y, r0.z, r0.w, r1.x, r1.y, r1.z, r1.w};
            float bb[4] = {bv.x, bv.y, bv.z, bv.w};
#pragma unroll
            for (int i = 0; i < 8; i++)
#pragma unroll
                for (int j = 0; j < 4; j++) acc[i][j] += av[i] * bb[j];
        }
        __syncthreads();
    }
    float b0 = bias[colb + tx * 4 + 0];
    float b1v = bias[colb + tx * 4 + 1];
    float b2v = bias[colb + tx * 4 + 2];
    float b3v = bias[colb + tx * 4 + 3];
#pragma unroll
    for (int i = 0; i < 8; i++) {
        float4 v;
        v.x = fmaxf(acc[i][0] + b0, 0.f);
        v.y = fmaxf(acc[i][1] + b1v, 0.f);
        v.z = fmaxf(acc[i][2] + b2v, 0.f);
        v.w = fmaxf(acc[i][3] + b3v, 0.f);
        *(float4*)&g_h[(size_t)(rowb + ty * 8 + i) * HH + colb + tx * 4] = v;
    }
}

__global__ __launch_bounds__(256) void k_prep(const float* __restrict__ x,
                                              const float* __restrict__ gw1,
                                              const float* __restrict__ gb1,
                                              const float* __restrict__ upw,
                                              const float* __restrict__ dww,
                                              __half* __restrict__ upwt,
                                              __half* __restrict__ dwwt) {
    __shared__ char sm[12288];
    const int b = blockIdx.x;
    const int tid = threadIdx.x;

    if (b < NB_GATE) {
        gate_body(x, gw1, gb1, b & 3, b >> 2, tid, sm);
    } else if (b < NB_GATE + NB_WUP) {
        const int idx = b - NB_GATE;
        // up_w [E][DD][FF] -> upwt [E][FF][DD]: grid (FF/32=64, DD/64=8, NE)
        wconv_body(upw, upwt, DD, FF, idx & 63, (idx >> 6) & 7, idx >> 9, tid, sm);
    } else if (b < NB_GATE + NB_WUP + NB_WDN) {
        const int idx = b - NB_GATE - NB_WUP;
        // down_w [E][FF][DD] -> dwwt [E][DD][FF]: grid (DD/32=16, FF/64=32, NE)
        wconv_body(dww, dwwt, FF, DD, idx & 15, (idx >> 4) & 31, idx >> 9, tid, sm);
    } else if (b < NB_GATE + NB_WUP + NB_WDN + NB_CVT) {
        const int idx = b - NB_GATE - NB_WUP - NB_WDN;
        const int i = idx * 256 + tid;
        float4 v = ((const float4*)x)[i];
        ((uint2*)g_xh)[i] = make_uint2(packh(v.x, v.y), packh(v.z, v.w));
    } else {
        if (tid < NE) { g_count[tid] = 0; g_usage[tid] = 0.f; }
    }
}

// ---------------- router ----------------
__global__ __launch_bounds__(256) void k_router(const float* __restrict__ w2,
                                                const float* __restrict__ b2,
                                                float* __restrict__ probs_out) {
    __shared__ float hs[16 * HH];
    __shared__ float w2s[HH * NE];
    __shared__ float usage_s[NE];
    const int tid  = threadIdx.x;
    const int tok0 = blockIdx.x * 16;
    for (int i = tid; i < 16 * HH; i += 256) hs[i] = g_h[(size_t)tok0 * HH + i];
    for (int i = tid; i < HH * NE; i += 256) w2s[i] = w2[i];
    if (tid < NE) usage_s[tid] = 0.f;
    __syncthreads();

    const int tl = tid >> 4;
    const int e  = tid & 15;
    float s = b2[e];
    const float* hr = &hs[tl * HH];
#pragma unroll 8
    for (int k = 0; k < HH; k++) s += hr[k] * w2s[k * NE + e];

    float z = s * 2.0f;
    float m = z;
#pragma unroll
    for (int off = 8; off; off >>= 1) m = fmaxf(m, __shfl_xor_sync(0xffffffffu, m, off, 16));
    float p = expf(z - m);
    float sum = p;
#pragma unroll
    for (int off = 8; off; off >>= 1) sum += __shfl_xor_sync(0xffffffffu, sum, off, 16);
    float prob = p / sum;

    const int tok = tok0 + tl;
    probs_out[(size_t)tok * NE + e] = prob;
    atomicAdd(&usage_s[e], prob);

    float v1 = prob; int i1 = e;
#pragma unroll
    for (int off = 8; off; off >>= 1) {
        float ov = __shfl_xor_sync(0xffffffffu, v1, off, 16);
        int   oi = __shfl_xor_sync(0xffffffffu, i1, off, 16);
        if (ov > v1 || (ov == v1 && oi < i1)) { v1 = ov; i1 = oi; }
    }
    float v2 = (e == i1) ? -1e30f : prob; int i2 = e;
#pragma unroll
    for (int off = 8; off; off >>= 1) {
        float ov = __shfl_xor_sync(0xffffffffu, v2, off, 16);
        int   oi = __shfl_xor_sync(0xffffffffu, i2, off, 16);
        if (ov > v2 || (ov == v2 && oi < i2)) { v2 = ov; i2 = oi; }
    }
    if (e == 0) {
        float e2  = expf(v2 - v1);
        float den = 1.f + e2;
        g_top_idx[tok * 2 + 0] = i1;
        g_top_idx[tok * 2 + 1] = i2;
        g_top_w[tok * 2 + 0] = 1.f / den;
        g_top_w[tok * 2 + 1] = e2 / den;
        atomicAdd(&g_count[i1], 1);
        atomicAdd(&g_count[i2], 1);
    }
    __syncthreads();
    if (tid < NE) atomicAdd(&g_usage[tid], usage_s[tid]);
}

// ---------------- dispatch (offsets + row init + scatter), single block ----------------
__global__ __launch_bounds__(256) void k_dispatch() {
    __shared__ int soff[NE + 1];
    __shared__ int sfill[NE];
    const int tid = threadIdx.x;
    if (tid == 0) {
        int acc = 0;
        for (int ee = 0; ee < NE; ee++) {
            soff[ee] = acc;
            acc += ((g_count[ee] + TMr - 1) / TMr) * TMr;
        }
        soff[NE] = acc;
        for (int ee = 0; ee <= NE; ee++) g_off[ee] = soff[ee];
    }
    if (tid < NE) sfill[tid] = 0;
    __syncthreads();
    for (int i = tid; i < MAXP; i += 256) {
        g_row_token[i] = -1;
        int ee = 0;
        while (ee < NE - 1 && i >= soff[ee + 1]) ee++;
        g_row_expert[i] = ee;
    }
    __syncthreads();
    for (int tok = tid; tok < NTOK; tok += 256) {
#pragma unroll
        for (int k = 0; k < TOPK; k++) {
            int   e = g_top_idx[tok * 2 + k];
            float w = g_top_w[tok * 2 + k];
            int pos = soff[e] + atomicAdd(&sfill[e], 1);
            g_row_token[pos] = tok;
            g_row_wt[pos]    = w;
            g_row_slot[pos]  = k;
        }
    }
}

// ================= mma.sync GEMM kernels (single fp16 A x B) =================
__device__ __forceinline__ void gemm_compute_chunk(uint32_t sb, int s,
                                                   uint32_t aOff, uint32_t bOff,
                                                   float acc[4][4][4]) {
    const uint32_t baseA = sb + SM_BUF + s * STAGE_SZ + A_HI;
    const uint32_t baseB = sb + SM_BUF + s * STAGE_SZ + B_HI;
#pragma unroll
    for (int k16 = 0; k16 < 2; k16++) {
        const uint32_t kb = k16 * 32;
        uint32_t bh0[4], bh1[4];
        ldm4(bh0, baseB + bOff + kb);
        ldm4(bh1, baseB + bOff + 16 * ROWB + kb);
#pragma unroll
        for (int mf = 0; mf < 4; mf++) {
            uint32_t ah[4];
            ldm4(ah, baseA + aOff + mf * (16 * ROWB) + kb);
            mma16816(acc[mf][0], ah, bh0[0], bh0[2]);
            mma16816(acc[mf][1], ah, bh0[1], bh0[3]);
            mma16816(acc[mf][2], ah, bh1[0], bh1[2]);
            mma16816(acc[mf][3], ah, bh1[1], bh1[3]);
        }
    }
}

// ---------------- up: gathered x @ up_w^T + bias -> gelu -> g_hid fp16 ----------------
__global__ __launch_bounds__(256, 1) void k_up(const float* __restrict__ upb) {
    extern __shared__ char smem[];
    const int rowb = blockIdx.y * TMr;
    if (rowb >= g_off[NE]) return;
    const int e    = g_row_expert[rowb];
    const int colb = blockIdx.x * TNc;
    const uint32_t sb = smem_u32(smem);
    const int tid = threadIdx.x, lane = tid & 31, wid = tid >> 5;
    const int warpM = wid >> 2, warpN = wid & 3;

    float* sBias = (float*)smem;
    if (tid < TNc) sBias[tid] = upb[(size_t)e * FF + colb + tid];

    const int irow = tid >> 1, ihalf = tid & 1;
    const int tok = g_row_token[rowb + irow];
    const uint32_t okA = (tok >= 0) ? 16u : 0u;
    const __half* sA = g_xh + (size_t)(tok < 0 ? 0 : tok) * DD;
    const __half* sB = g_upwt + ((size_t)e * FF + colb + irow) * DD;
    const uint32_t dRow = sb + SM_BUF + irow * ROWB + ihalf * 32;

    float acc[4][4][4];
#pragma unroll
    for (int a = 0; a < 4; a++)
#pragma unroll
        for (int b = 0; b < 4; b++)
#pragma unroll
            for (int c = 0; c < 4; c++) acc[a][b][c] = 0.f;

    const int NC = DD / CK;  // 16
#pragma unroll 1
    for (int c = 0; c < STAGES - 1; c++) {
        const int k0 = c * CK + ihalf * 16;
        const uint32_t st = dRow + (c % STAGES) * STAGE_SZ;
        cpa16(st + A_HI,      sA + k0,     okA);
        cpa16(st + A_HI + 16, sA + k0 + 8, okA);
        cpa16(st + B_HI,      sB + k0,     16);
        cpa16(st + B_HI + 16, sB + k0 + 8, 16);
        cpa_commit();
    }

    const uint32_t lrow = lane & 15, lcol = (lane >> 4) * 16;
    const uint32_t aOff = (warpM * 64 + lrow) * ROWB + lcol;
    const uint32_t bOff = (warpN * 32 + lrow) * ROWB + lcol;

#pragma unroll 1
    for (int c = 0; c < NC; c++) {
        cpa_waitS();
        __syncthreads();
        const int nc = c + STAGES - 1;
        if (nc < NC) {
            const int k0 = nc * CK + ihalf * 16;
            const uint32_t st = dRow + (nc % STAGES) * STAGE_SZ;
            cpa16(st + A_HI,      sA + k0,     okA);
            cpa16(st + A_HI + 16, sA + k0 + 8, okA);
            cpa16(st + B_HI,      sB + k0,     16);
            cpa16(st + B_HI + 16, sB + k0 + 8, 16);
        }
        cpa_commit();
        gemm_compute_chunk(sb, c % STAGES, aOff, bOff, acc);
    }

    // epilogue: bias + GELU -> g_hid fp16
    const int g = lane >> 2, tq = lane & 3;
#pragma unroll
    for (int mf = 0; mf < 4; mf++) {
        const size_t r0 = (size_t)(rowb + warpM * 64 + mf * 16 + g);
#pragma unroll
        for (int nf = 0; nf < 4; nf++) {
            const int cl = warpN * 32 + nf * 8 + 2 * tq;
            const float b0 = sBias[cl], b1 = sBias[cl + 1];
            float v0 = gelu_f(acc[mf][nf][0] + b0);
            float v1 = gelu_f(acc[mf][nf][1] + b1);
            float v2 = gelu_f(acc[mf][nf][2] + b0);
            float v3 = gelu_f(acc[mf][nf][3] + b1);
            *(uint32_t*)(g_hid + r0 * FF + colb + cl) = packh(v0, v1);
            *(uint32_t*)(g_hid + (r0 + 8) * FF + colb + cl) = packh(v2, v3);
        }
    }
}

// ---------------- down: hid @ down_w^T + bias, weighted write to per-slot partials ----------------
__global__ __launch_bounds__(256, 1) void k_down(const float* __restrict__ dwb) {
    extern __shared__ char smem[];
    const int rowb = blockIdx.y * TMr;
    if (rowb >= g_off[NE]) return;
    const int e    = g_row_expert[rowb];
    const int colb = blockIdx.x * TNc;
    const uint32_t sb = smem_u32(smem);
    const int tid = threadIdx.x, lane = tid & 31, wid = tid >> 5;
    const int warpM = wid >> 2, warpN = wid & 3;

    float* sBias = (float*)smem;
    if (tid < TNc) sBias[tid] = dwb[(size_t)e * DD + colb + tid];

    const int irow = tid >> 1, ihalf = tid & 1;
    const __half* sA = g_hid + (size_t)(rowb + irow) * FF;
    const __half* sB = g_dwwt + ((size_t)e * DD + colb + irow) * FF;
    const uint32_t dRow = sb + SM_BUF + irow * ROWB + ihalf * 32;

    float acc[4][4][4];
#pragma unroll
    for (int a = 0; a < 4; a++)
#pragma unroll
        for (int b = 0; b < 4; b++)
#pragma unroll
            for (int c = 0; c < 4; c++) acc[a][b][c] = 0.f;

    const int NC = FF / CK;  // 64
#pragma unroll 1
    for (int c = 0; c < STAGES - 1; c++) {
        const int k0 = c * CK + ihalf * 16;
        const uint32_t st = dRow + (c % STAGES) * STAGE_SZ;
        cpa16(st + A_HI,      sA + k0,     16);
        cpa16(st + A_HI + 16, sA + k0 + 8, 16);
        cpa16(st + B_HI,      sB + k0,     16);
        cpa16(st + B_HI + 16, sB + k0 + 8, 16);
        cpa_commit();
    }

    const uint32_t lrow = lane & 15, lcol = (lane >> 4) * 16;
    const uint32_t aOff = (warpM * 64 + lrow) * ROWB + lcol;
    const uint32_t bOff = (warpN * 32 + lrow) * ROWB + lcol;

#pragma unroll 1
    for (int c = 0; c < NC; c++) {
        cpa_waitS();
        __syncthreads();
        const int nc = c + STAGES - 1;
        if (nc < NC) {
            const int k0 = nc * CK + ihalf * 16;
            const uint32_t st = dRow + (nc % STAGES) * STAGE_SZ;
            cpa16(st + A_HI,      sA + k0,     16);
            cpa16(st + A_HI + 16, sA + k0 + 8, 16);
            cpa16(st + B_HI,      sB + k0,     16);
            cpa16(st + B_HI + 16, sB + k0 + 8, 16);
        }
        cpa_commit();
        gemm_compute_chunk(sb, c % STAGES, aOff, bOff, acc);
    }

    // epilogue: bias + weight, write per-slot partials
    const int g = lane >> 2, tq = lane & 3;
#pragma unroll
    for (int mf = 0; mf < 4; mf++) {
        const int rA = rowb + warpM * 64 + mf * 16 + g;
        const int rB = rA + 8;
        const int tokA = g_row_token[rA];
        const int tokB = g_row_token[rB];
        const float wtA = g_row_wt[rA], wtB = g_row_wt[rB];
        const int slA = (tokA >= 0) ? g_row_slot[rA] : 0;
        const int slB = (tokB >= 0) ? g_row_slot[rB] : 0;
#pragma unroll
        for (int nf = 0; nf < 4; nf++) {
            const int cl = warpN * 32 + nf * 8 + 2 * tq;
            const float b0 = sBias[cl], b1 = sBias[cl + 1];
            if (tokA >= 0) {
                float2 v = make_float2((acc[mf][nf][0] + b0) * wtA,
                                       (acc[mf][nf][1] + b1) * wtA);
                *(float2*)(&g_partial[slA][0] + (size_t)tokA * DD + colb + cl) = v;
            }
            if (tokB >= 0) {
                float2 v = make_float2((acc[mf][nf][2] + b0) * wtB,
                                       (acc[mf][nf][3] + b1) * wtB);
                *(float2*)(&g_partial[slB][0] + (size_t)tokB * DD + colb + cl) = v;
            }
        }
    }
}

// ---------------- combine two slots ----------------
__global__ void k_combine(float* __restrict__ out) {
    int i = blockIdx.x * blockDim.x + threadIdx.x;
    float4 a = ((const float4*)&g_partial[0][0])[i];
    float4 b = ((const float4*)&g_partial[1][0])[i];
    ((float4*)out)[i] = make_float4(a.x + b.x, a.y + b.y, a.z + b.z, a.w + b.w);
}

// ---------------- load-balance loss ----------------
__global__ void k_fin(float* __restrict__ out) {
    int t = threadIdx.x;
    float v = 0.f;
    if (t < NE) {
        float u = g_usage[t] * (1.0f / NTOK);
        float d = u - (1.0f / NE);
        v = d * d;
    }
#pragma unroll
    for (int off = 16; off; off >>= 1) v += __shfl_down_sync(0xffffffffu, v, off);
    if (t == 0) out[(size_t)NTOK * DD] = v * (1.0f / NE);
}

// ---------------- launch ----------------
extern "C" void kernel_launch(void* const* d_in, const int* in_sizes, int n_in,
                              void* d_out, int out_size) {
    const float* x   = (const float*)d_in[0];
    const float* gw1 = (const float*)d_in[1];
    const float* gb1 = (const float*)d_in[2];
    const float* gw2 = (const float*)d_in[3];
    const float* gb2 = (const float*)d_in[4];
    const float* upw = (const float*)d_in[5];
    const float* upb = (const float*)d_in[6];
    const float* dww = (const float*)d_in[7];
    const float* dwb = (const float*)d_in[8];
    float* out   = (float*)d_out;
    float* probs = out + (size_t)NTOK * DD + 1;

    static int smem_set = 0;
    if (!smem_set) {
        cudaFuncSetAttribute(k_up,   cudaFuncAttributeMaxDynamicSharedMemorySize, SMEM_DYN);
        cudaFuncSetAttribute(k_down, cudaFuncAttributeMaxDynamicSharedMemorySize, SMEM_DYN);
        smem_set = 1;
    }

    __half *upwt, *dwwt;
    cudaGetSymbolAddress((void**)&upwt, g_upwt);
    cudaGetSymbolAddress((void**)&dwwt, g_dwwt);

    k_prep<<<NB_PREP, 256>>>(x, gw1, gb1, upw, dww, upwt, dwwt);
    k_router<<<NTOK / 16, 256>>>(gw2, gb2, probs);
    k_dispatch<<<1, 256>>>();
    k_up<<<dim3(FF / TNc, NROWTILES), 256, SMEM_DYN>>>(upb);
    k_down<<<dim3(DD / TNc, NROWTILES), 256, SMEM_DYN>>>(dwb);
    k_combine<<<(NTOK * DD / 4) / 256, 256>>>(out);
    k_fin<<<1, 32>>>(out);
}